// round 4
// baseline (speedup 1.0000x reference)
#include <cuda_runtime.h>
#include <math.h>

// Problem constants
#define BT   2048      // B*T tokens
#define TT   1024      // T
#define DD   768       // model dim
#define HH   12        // heads
#define HS   64        // head size
#define NKV  3         // kv heads
#define NL   12        // layers
#define II   2048      // mlp dim
#define VV   50257     // vocab
#define KVD  (NKV*HS)  // 192
#define EPS_ 1e-6f

// ---------------- scratch (static device globals: no allocation) ----------------
__device__ float g_x[BT * DD];
__device__ float g_h[BT * DD];
__device__ float g_q[BT * DD];
__device__ float g_k[BT * KVD];
__device__ float g_v[BT * KVD];
__device__ float g_y[BT * DD];
__device__ float g_gate[BT * II];
__device__ float g_up[BT * II];

// ---------------- embedding gather ----------------
__global__ void embed_kernel(const int* __restrict__ idx,
                             const float* __restrict__ embed) {
    int row = blockIdx.x;                 // token
    int t4  = threadIdx.x;                // 192 threads, one float4 each
    const float4* src = (const float4*)(embed + (size_t)idx[row] * DD);
    ((float4*)(g_x + (size_t)row * DD))[t4] = src[t4];
}

// ---------------- RMSNorm ----------------
__global__ __launch_bounds__(256) void rmsnorm_kernel(const float* __restrict__ in,
                                                      const float* __restrict__ w,
                                                      float* __restrict__ out) {
    int row = blockIdx.x;
    const float* x = in + (size_t)row * DD;
    float s = 0.f;
    for (int i = threadIdx.x; i < DD; i += 256) { float v = x[i]; s += v * v; }
    #pragma unroll
    for (int o = 16; o; o >>= 1) s += __shfl_xor_sync(0xffffffffu, s, o);
    __shared__ float red[8];
    if ((threadIdx.x & 31) == 0) red[threadIdx.x >> 5] = s;
    __syncthreads();
    if (threadIdx.x < 8) {
        s = red[threadIdx.x];
        #pragma unroll
        for (int o = 4; o; o >>= 1) s += __shfl_xor_sync(0xffu, s, o);
        if (threadIdx.x == 0) red[0] = s;
    }
    __syncthreads();
    float inv = rsqrtf(red[0] / (float)DD + EPS_);
    for (int i = threadIdx.x; i < DD; i += 256)
        out[(size_t)row * DD + i] = w[i] * x[i] * inv;
}

// ---------------- tiled SGEMM: C[M,N] = A[M,K] @ B ----------------
// TRANSB==0: B is [K,N] row-major. TRANSB==1: B is [N,K] row-major (B^T logical).
// ACCUM==1: C += result (residual add). M % 128 == 0 and K % 16 == 0 assumed; N guarded.
template<int TRANSB, int ACCUM>
__global__ __launch_bounds__(256) void sgemm(const float* __restrict__ A,
                                             const float* __restrict__ B,
                                             float* __restrict__ C,
                                             int M, int N, int K) {
    __shared__ float As[16][132];
    __shared__ float Bs[16][132];
    int tid = threadIdx.x;
    int tx = tid & 15, ty = tid >> 4;
    int col0 = blockIdx.x * 128;
    int row0 = blockIdx.y * 128;
    float acc[8][8];
    #pragma unroll
    for (int i = 0; i < 8; i++)
        #pragma unroll
        for (int j = 0; j < 8; j++) acc[i][j] = 0.f;

    for (int k0 = 0; k0 < K; k0 += 16) {
        // A tile: 128 rows x 16 k, float4 along K, store transposed
        #pragma unroll
        for (int i = 0; i < 2; i++) {
            int f = tid + i * 256;          // 0..511
            int r = f >> 2;                 // 0..127
            int kk = (f & 3) * 4;           // 0,4,8,12
            float4 v = *(const float4*)(A + (size_t)(row0 + r) * K + k0 + kk);
            As[kk + 0][r] = v.x; As[kk + 1][r] = v.y;
            As[kk + 2][r] = v.z; As[kk + 3][r] = v.w;
        }
        if (!TRANSB) {
            // B[K,N] tile: 16 k-rows x 128 n, float4 along N
            #pragma unroll
            for (int i = 0; i < 2; i++) {
                int f = tid + i * 256;
                int kk = f >> 5;            // 0..15
                int n  = (f & 31) * 4;      // 0..124
                int gn = col0 + n;
                float4 v = make_float4(0.f, 0.f, 0.f, 0.f);
                if (gn < N)  // all non-trans Ns are multiples of 4
                    v = *(const float4*)(B + (size_t)(k0 + kk) * N + gn);
                *(float4*)&Bs[kk][n] = v;
            }
        } else {
            // B[N,K] tile: 128 n-rows x 16 k, float4 along K, store transposed
            #pragma unroll
            for (int i = 0; i < 2; i++) {
                int f = tid + i * 256;
                int n  = f >> 2;            // 0..127
                int kk = (f & 3) * 4;
                int gn = col0 + n;
                float4 v = make_float4(0.f, 0.f, 0.f, 0.f);
                if (gn < N)
                    v = *(const float4*)(B + (size_t)gn * K + k0 + kk);
                Bs[kk + 0][n] = v.x; Bs[kk + 1][n] = v.y;
                Bs[kk + 2][n] = v.z; Bs[kk + 3][n] = v.w;
            }
        }
        __syncthreads();
        #pragma unroll
        for (int kk = 0; kk < 16; kk++) {
            float4 a0 = *(const float4*)&As[kk][ty * 8];
            float4 a1 = *(const float4*)&As[kk][ty * 8 + 4];
            float4 b0 = *(const float4*)&Bs[kk][tx * 8];
            float4 b1 = *(const float4*)&Bs[kk][tx * 8 + 4];
            float a[8] = {a0.x, a0.y, a0.z, a0.w, a1.x, a1.y, a1.z, a1.w};
            float b[8] = {b0.x, b0.y, b0.z, b0.w, b1.x, b1.y, b1.z, b1.w};
            #pragma unroll
            for (int i = 0; i < 8; i++)
                #pragma unroll
                for (int j = 0; j < 8; j++) acc[i][j] += a[i] * b[j];
        }
        __syncthreads();
    }
    #pragma unroll
    for (int i = 0; i < 8; i++) {
        int r = row0 + ty * 8 + i;
        #pragma unroll
        for (int j = 0; j < 8; j++) {
            int c = col0 + tx * 8 + j;
            if (c < N) {
                size_t o = (size_t)r * N + c;
                if (ACCUM) C[o] += acc[i][j];
                else       C[o]  = acc[i][j];
            }
        }
    }
}

// ---------------- RoPE (full 64-dim rotation, q: 12 heads, k: 3 heads) ----------------
__global__ void rope_kernel() {
    int row = blockIdx.x;
    int t = row % TT;
    int i = threadIdx.x;                 // 480 = (12+3)*32
    int head = i >> 5;
    int d = i & 31;
    float freq = powf(10000.f, (float)d / 32.0f);
    float ang = (float)t / freq;
    float s, c;
    sincosf(ang, &s, &c);
    float* p;
    if (head < HH) p = g_q + (size_t)row * DD + head * HS;
    else           p = g_k + (size_t)row * KVD + (head - HH) * HS;
    float xr = p[d], xi = p[d + 32];
    p[d]      = xr * c - xi * s;
    p[d + 32] = xi * c + xr * s;
}

// ---------------- fused causal attention (online softmax, 64-query tiles) ----------------
// smem layout (dynamic): Qs[64][68] | KtPs[64][68] (K^T, aliased with P) | Vs[64][68]
#define ATN_STRIDE 68
#define ATN_SMEM   (3 * 64 * ATN_STRIDE * 4)

__global__ __launch_bounds__(256) void attn_kernel() {
    extern __shared__ float sm[];
    float (*Qs)[ATN_STRIDE]   = (float(*)[ATN_STRIDE])sm;
    float (*KtPs)[ATN_STRIDE] = (float(*)[ATN_STRIDE])(sm + 64 * ATN_STRIDE);
    float (*Vs)[ATN_STRIDE]   = (float(*)[ATN_STRIDE])(sm + 2 * 64 * ATN_STRIDE);

    int q0 = blockIdx.x * 64;
    int b = blockIdx.y / HH, h = blockIdx.y % HH;
    int kvh = h % NKV;                    // reference tiles as (REP, NKV): kv = h % NKV
    int tid = threadIdx.x;
    int r = tid >> 2, g = tid & 3;        // row 0..63, col-group 0..3 (16 cols each)

    // load Q tile [64 rows][64 dims]
    #pragma unroll
    for (int i = 0; i < 4; i++) {
        int f = tid + i * 256;
        int rr = f >> 4, c4 = (f & 15) * 4;
        float4 v = *(const float4*)(g_q + (size_t)(b * TT + q0 + rr) * DD + h * HS + c4);
        Qs[rr][c4] = v.x; Qs[rr][c4 + 1] = v.y; Qs[rr][c4 + 2] = v.z; Qs[rr][c4 + 3] = v.w;
    }

    float O[16];
    #pragma unroll
    for (int j = 0; j < 16; j++) O[j] = 0.f;
    float m = -1e30f, l = 0.f;
    const float scale = 0.125f;           // 1/sqrt(64)

    for (int s0 = 0; s0 <= q0; s0 += 64) {
        __syncthreads();   // previous-iter reads of KtPs/Vs complete (also covers Q load, iter 0)
        // load K tile transposed -> KtPs[d][key], V tile natural -> Vs[key][d]
        #pragma unroll
        for (int i = 0; i < 4; i++) {
            int f = tid + i * 256;
            int rr = f >> 4, c4 = (f & 15) * 4;
            size_t base = (size_t)(b * TT + s0 + rr) * KVD + kvh * HS + c4;
            float4 kv = *(const float4*)(g_k + base);
            KtPs[c4][rr] = kv.x; KtPs[c4 + 1][rr] = kv.y;
            KtPs[c4 + 2][rr] = kv.z; KtPs[c4 + 3][rr] = kv.w;
            float4 vv = *(const float4*)(g_v + base);
            Vs[rr][c4] = vv.x; Vs[rr][c4 + 1] = vv.y; Vs[rr][c4 + 2] = vv.z; Vs[rr][c4 + 3] = vv.w;
        }
        __syncthreads();

        // S[r][g*16+j] = scale * Q[r,:] . K[g*16+j,:]
        float sv[16];
        #pragma unroll
        for (int j = 0; j < 16; j++) sv[j] = 0.f;
        #pragma unroll 4
        for (int d = 0; d < 64; d++) {
            float qd = Qs[r][d];
            #pragma unroll
            for (int j = 0; j < 16; j++) sv[j] += qd * KtPs[d][g * 16 + j];
        }
        #pragma unroll
        for (int j = 0; j < 16; j++) {
            int key = s0 + g * 16 + j;
            sv[j] = (key <= q0 + r) ? sv[j] * scale : -1e30f;
        }
        // row max across the 4-thread quad
        float mx = sv[0];
        #pragma unroll
        for (int j = 1; j < 16; j++) mx = fmaxf(mx, sv[j]);
        mx = fmaxf(mx, __shfl_xor_sync(0xffffffffu, mx, 1));
        mx = fmaxf(mx, __shfl_xor_sync(0xffffffffu, mx, 2));
        float m_new = fmaxf(m, mx);
        float corr = __expf(m - m_new);

        __syncthreads();   // everyone done reading K^T before we overwrite it with P

        float ssum = 0.f;
        #pragma unroll
        for (int j = 0; j < 16; j++) {
            float p = __expf(sv[j] - m_new);
            KtPs[r][g * 16 + j] = p;      // P aliased over K^T region
            ssum += p;
        }
        ssum += __shfl_xor_sync(0xffffffffu, ssum, 1);
        ssum += __shfl_xor_sync(0xffffffffu, ssum, 2);
        l = l * corr + ssum;
        m = m_new;
        #pragma unroll
        for (int j = 0; j < 16; j++) O[j] *= corr;
        __syncwarp();      // P row r written only by this quad (same warp)

        // O[r][c] += sum_s P[r][s] * V[s][c]
        #pragma unroll 4
        for (int s = 0; s < 64; s++) {
            float p = KtPs[r][s];
            #pragma unroll
            for (int j = 0; j < 16; j++) O[j] += p * Vs[s][g * 16 + j];
        }
    }

    float invl = 1.f / l;
    size_t obase = (size_t)(b * TT + q0 + r) * DD + h * HS + g * 16;
    #pragma unroll
    for (int j = 0; j < 16; j++) g_y[obase + j] = O[j] * invl;
}

// ---------------- SiLU(gate) * up ----------------
__global__ void silu_mul_kernel() {
    int i = blockIdx.x * 256 + threadIdx.x;
    float gv = g_gate[i];
    g_gate[i] = gv / (1.f + __expf(-gv)) * g_up[i];
}

// ---------------- host: launch the whole forward pass ----------------
extern "C" void kernel_launch(void* const* d_in, const int* in_sizes, int n_in,
                              void* d_out, int out_size) {
    const int*   idx   = (const int*)d_in[0];
    const float* embed = (const float*)d_in[1];
    const float* ln1   = (const float*)d_in[2];
    const float* qw    = (const float*)d_in[3];
    const float* kw    = (const float*)d_in[4];
    const float* vw    = (const float*)d_in[5];
    const float* ow    = (const float*)d_in[6];
    const float* ln2   = (const float*)d_in[7];
    const float* gw    = (const float*)d_in[8];
    const float* uw    = (const float*)d_in[9];
    const float* dw    = (const float*)d_in[10];
    const float* nw    = (const float*)d_in[11];
    float* out = (float*)d_out;

    float *px, *ph, *pq, *pk, *pv, *py, *pg, *pu;
    cudaGetSymbolAddress((void**)&px, g_x);
    cudaGetSymbolAddress((void**)&ph, g_h);
    cudaGetSymbolAddress((void**)&pq, g_q);
    cudaGetSymbolAddress((void**)&pk, g_k);
    cudaGetSymbolAddress((void**)&pv, g_v);
    cudaGetSymbolAddress((void**)&py, g_y);
    cudaGetSymbolAddress((void**)&pg, g_gate);
    cudaGetSymbolAddress((void**)&pu, g_up);

    cudaFuncSetAttribute(attn_kernel, cudaFuncAttributeMaxDynamicSharedMemorySize, ATN_SMEM);

    dim3 gq((DD + 127) / 128, BT / 128);      // (6,16)
    dim3 gkv((KVD + 127) / 128, BT / 128);    // (2,16)
    dim3 gi((II + 127) / 128, BT / 128);      // (16,16)
    dim3 ga(TT / 64, 2 * HH);                 // (16,24)
    dim3 gl((VV + 127) / 128, BT / 128);      // (393,16)

    embed_kernel<<<BT, 192>>>(idx, embed);

    for (int l = 0; l < NL; l++) {
        rmsnorm_kernel<<<BT, 256>>>(px, ln1 + (size_t)l * DD, ph);
        sgemm<0, 0><<<gq, 256>>>(ph, qw + (size_t)l * DD * DD, pq, BT, DD, DD);
        sgemm<0, 0><<<gkv, 256>>>(ph, kw + (size_t)l * DD * KVD, pk, BT, KVD, DD);
        sgemm<0, 0><<<gkv, 256>>>(ph, vw + (size_t)l * DD * KVD, pv, BT, KVD, DD);
        rope_kernel<<<BT, 480>>>();
        attn_kernel<<<ga, 256, ATN_SMEM>>>();
        sgemm<0, 1><<<gq, 256>>>(py, ow + (size_t)l * DD * DD, px, BT, DD, DD);   // x += y @ o_w
        rmsnorm_kernel<<<BT, 256>>>(px, ln2 + (size_t)l * DD, ph);
        sgemm<0, 0><<<gi, 256>>>(ph, gw + (size_t)l * DD * II, pg, BT, II, DD);
        sgemm<0, 0><<<gi, 256>>>(ph, uw + (size_t)l * DD * II, pu, BT, II, DD);
        silu_mul_kernel<<<(BT * II) / 256, 256>>>();
        sgemm<0, 1><<<gq, 256>>>(pg, dw + (size_t)l * II * DD, px, BT, DD, II);   // x += mlp
    }

    rmsnorm_kernel<<<BT, 256>>>(px, nw, ph);
    sgemm<1, 0><<<gl, 256>>>(ph, embed, out, BT, VV, DD);                          // logits = h @ embed^T
}

// round 6
// speedup vs baseline: 1.5913x; 1.5913x over previous
#include <cuda_runtime.h>
#include <cuda_bf16.h>
#include <math.h>
#include <stdint.h>

// Problem constants
#define BT   2048
#define TT   1024
#define DD   768
#define HH   12
#define HS   64
#define NKV  3
#define NL   12
#define II   2048
#define VV   50257
#define KVD  192
#define EPS_ 1e-6f

// ---------------- fp32 scratch ----------------
__device__ float g_x[BT * DD];
__device__ float g_q[BT * DD];
__device__ float g_k[BT * KVD];
__device__ float g_v[BT * KVD];
__device__ float g_gate[BT * II];
__device__ float g_up[BT * II];

// ---------------- bf16 split activations ----------------
__device__ __nv_bfloat16 g_hh[BT * DD], g_hl[BT * DD];   // rmsnorm out
__device__ __nv_bfloat16 g_yh[BT * DD], g_yl[BT * DD];   // attention out
__device__ __nv_bfloat16 g_ah[BT * II], g_al[BT * II];   // silu*up out

// ---------------- bf16 split weights (filled by prologue pass) ----------------
__device__ __nv_bfloat16 s_qw_h[NL * DD * DD],  s_qw_l[NL * DD * DD];
__device__ __nv_bfloat16 s_kw_h[NL * DD * KVD], s_kw_l[NL * DD * KVD];
__device__ __nv_bfloat16 s_vw_h[NL * DD * KVD], s_vw_l[NL * DD * KVD];
__device__ __nv_bfloat16 s_ow_h[NL * DD * DD],  s_ow_l[NL * DD * DD];
__device__ __nv_bfloat16 s_gw_h[NL * DD * II],  s_gw_l[NL * DD * II];
__device__ __nv_bfloat16 s_uw_h[NL * DD * II],  s_uw_l[NL * DD * II];
__device__ __nv_bfloat16 s_dw_h[NL * II * DD],  s_dw_l[NL * II * DD];
__device__ __nv_bfloat16 s_em_h[(size_t)VV * DD], s_em_l[(size_t)VV * DD];

// ---------------- helpers ----------------
__device__ __forceinline__ void bf16_split(float v, __nv_bfloat16& h, __nv_bfloat16& l) {
    h = __float2bfloat16(v);
    l = __float2bfloat16(v - __bfloat162float(h));
}

__device__ __forceinline__ void ldmx4(uint32_t* r, uint32_t a) {
    asm volatile("ldmatrix.sync.aligned.m8n8.x4.shared.b16 {%0,%1,%2,%3}, [%4];"
                 : "=r"(r[0]), "=r"(r[1]), "=r"(r[2]), "=r"(r[3]) : "r"(a));
}
__device__ __forceinline__ void ldmx4t(uint32_t* r, uint32_t a) {
    asm volatile("ldmatrix.sync.aligned.m8n8.x4.trans.shared.b16 {%0,%1,%2,%3}, [%4];"
                 : "=r"(r[0]), "=r"(r[1]), "=r"(r[2]), "=r"(r[3]) : "r"(a));
}
__device__ __forceinline__ void mma16816(float* c, const uint32_t* a, const uint32_t* b) {
    asm volatile("mma.sync.aligned.m16n8k16.row.col.f32.bf16.bf16.f32 "
                 "{%0,%1,%2,%3}, {%4,%5,%6,%7}, {%8,%9}, {%0,%1,%2,%3};"
                 : "+f"(c[0]), "+f"(c[1]), "+f"(c[2]), "+f"(c[3])
                 : "r"(a[0]), "r"(a[1]), "r"(a[2]), "r"(a[3]), "r"(b[0]), "r"(b[1]));
}

// ---------------- fp32 -> bf16 hi/lo splitter (vectorized) ----------------
__global__ void split_kernel(const float* __restrict__ s,
                             __nv_bfloat16* __restrict__ h,
                             __nv_bfloat16* __restrict__ l, int n4) {
    int i = blockIdx.x * 256 + threadIdx.x;
    if (i >= n4) return;
    float4 v = ((const float4*)s)[i];
    __nv_bfloat16 h0, h1, h2, h3, l0, l1, l2, l3;
    bf16_split(v.x, h0, l0); bf16_split(v.y, h1, l1);
    bf16_split(v.z, h2, l2); bf16_split(v.w, h3, l3);
    __nv_bfloat162* hp = (__nv_bfloat162*)(h + (size_t)i * 4);
    __nv_bfloat162* lp = (__nv_bfloat162*)(l + (size_t)i * 4);
    hp[0] = __halves2bfloat162(h0, h1); hp[1] = __halves2bfloat162(h2, h3);
    lp[0] = __halves2bfloat162(l0, l1); lp[1] = __halves2bfloat162(l2, l3);
}

// ---------------- embedding gather ----------------
__global__ void embed_kernel(const int* __restrict__ idx,
                             const float* __restrict__ embed) {
    int row = blockIdx.x;
    int t4  = threadIdx.x;
    const float4* src = (const float4*)(embed + (size_t)idx[row] * DD);
    ((float4*)(g_x + (size_t)row * DD))[t4] = src[t4];
}

// ---------------- RMSNorm -> bf16 hi/lo ----------------
__global__ __launch_bounds__(256) void rmsnorm_split(const float* __restrict__ in,
                                                     const float* __restrict__ w,
                                                     __nv_bfloat16* __restrict__ oh,
                                                     __nv_bfloat16* __restrict__ ol) {
    int row = blockIdx.x;
    const float* x = in + (size_t)row * DD;
    float s = 0.f;
    for (int i = threadIdx.x; i < DD; i += 256) { float v = x[i]; s += v * v; }
    #pragma unroll
    for (int o = 16; o; o >>= 1) s += __shfl_xor_sync(0xffffffffu, s, o);
    __shared__ float red[8];
    if ((threadIdx.x & 31) == 0) red[threadIdx.x >> 5] = s;
    __syncthreads();
    if (threadIdx.x < 8) {
        s = red[threadIdx.x];
        #pragma unroll
        for (int o = 4; o; o >>= 1) s += __shfl_xor_sync(0xffu, s, o);
        if (threadIdx.x == 0) red[0] = s;
    }
    __syncthreads();
    float inv = rsqrtf(red[0] / (float)DD + EPS_);
    for (int i = threadIdx.x; i < DD; i += 256) {
        float r = w[i] * x[i] * inv;
        __nv_bfloat16 h, l;
        bf16_split(r, h, l);
        oh[(size_t)row * DD + i] = h;
        ol[(size_t)row * DD + i] = l;
    }
}

// ---------------- bf16x3 tensor-core GEMM ----------------
// C[M,N] = A[M,K] @ B (+C if ACCUM). A: bf16 hi/lo split, row-major [M,K].
// TRANSB==0: B is [K,N]. TRANSB==1: B is [N,K]. Both bf16 hi/lo split.
// Block tile 128x128, BK=32. 8 warps as 2(m) x 4(n); warp tile 64x32.
template<int TRANSB, int ACCUM>
__global__ __launch_bounds__(256) void bgemm(const __nv_bfloat16* __restrict__ Ah,
                                             const __nv_bfloat16* __restrict__ Al,
                                             const __nv_bfloat16* __restrict__ Bh,
                                             const __nv_bfloat16* __restrict__ Bl,
                                             float* __restrict__ C,
                                             int M, int N, int K) {
    constexpr int AST   = 40;                    // As row stride (bf16)
    constexpr int BROWS = TRANSB ? 128 : 32;
    constexpr int BST   = TRANSB ? 40  : 136;    // Bs row stride (bf16)

    __shared__ __nv_bfloat16 As_h[128 * AST], As_l[128 * AST];
    __shared__ __nv_bfloat16 Bs_h[BROWS * BST], Bs_l[BROWS * BST];

    int tid  = threadIdx.x;
    int lane = tid & 31, wid = tid >> 5;
    int wm = wid >> 2, wn = wid & 3;             // warp grid 2 x 4
    int row0 = blockIdx.y * 128, col0 = blockIdx.x * 128;

    float c[4][4][4] = {};

    uint32_t sAh = (uint32_t)__cvta_generic_to_shared(As_h);
    uint32_t sAl = (uint32_t)__cvta_generic_to_shared(As_l);
    uint32_t sBh = (uint32_t)__cvta_generic_to_shared(Bs_h);
    uint32_t sBl = (uint32_t)__cvta_generic_to_shared(Bs_l);

    // fill indices
    int am = tid >> 2, aq = (tid & 3) * 8;       // A: rows am, am+64; 8 bf16 chunk aq

    for (int k0 = 0; k0 < K; k0 += 32) {
        // ---- A tile fill (straight copy, [m][k]) ----
        #pragma unroll
        for (int i = 0; i < 2; i++) {
            int m = am + i * 64;
            size_t g = (size_t)(row0 + m) * K + k0 + aq;
            *(uint4*)&As_h[m * AST + aq] = *(const uint4*)&Ah[g];
            *(uint4*)&As_l[m * AST + aq] = *(const uint4*)&Al[g];
        }
        // ---- B tile fill ----
        if (!TRANSB) {
            // B[K,N] -> Bs[k][n]
            #pragma unroll
            for (int i = 0; i < 2; i++) {
                int k = (tid >> 4) + i * 16;
                int q = (tid & 15) * 8;
                uint4 vh = make_uint4(0,0,0,0), vl = make_uint4(0,0,0,0);
                if (col0 + q < N) {                     // N multiple of 8 here
                    size_t g = (size_t)(k0 + k) * N + col0 + q;
                    vh = *(const uint4*)&Bh[g];
                    vl = *(const uint4*)&Bl[g];
                }
                *(uint4*)&Bs_h[k * BST + q] = vh;
                *(uint4*)&Bs_l[k * BST + q] = vl;
            }
        } else {
            // B[N,K] -> Bs[n][k]
            #pragma unroll
            for (int i = 0; i < 2; i++) {
                int n = (tid >> 2) + i * 64;
                int q = (tid & 3) * 8;
                uint4 vh = make_uint4(0,0,0,0), vl = make_uint4(0,0,0,0);
                if (col0 + n < N) {
                    size_t g = (size_t)(col0 + n) * K + k0 + q;
                    vh = *(const uint4*)&Bh[g];
                    vl = *(const uint4*)&Bl[g];
                }
                *(uint4*)&Bs_h[n * BST + q] = vh;
                *(uint4*)&Bs_l[n * BST + q] = vl;
            }
        }
        __syncthreads();

        #pragma unroll
        for (int kk = 0; kk < 32; kk += 16) {
            uint32_t fah[4][4], fal[4][4], fbh[2][4], fbl[2][4];

            // A fragments: ldmatrix.x4 per 16x16 tile (non-trans)
            int abase = ((wm * 64 + (lane & 15)) * AST + (lane >> 4) * 8 + kk) * 2;
            #pragma unroll
            for (int mf = 0; mf < 4; mf++) {
                ldmx4(fah[mf], sAh + abase + mf * 16 * AST * 2);
                ldmx4(fal[mf], sAl + abase + mf * 16 * AST * 2);
            }
            // B fragments: two x4 loads cover 4 n-frags (n8 each)
            if (!TRANSB) {
                int bbase = (((lane & 7) + ((lane >> 3) & 1) * 8 + kk) * BST
                             + wn * 32 + ((lane >> 4) & 1) * 8) * 2;
                ldmx4t(fbh[0], sBh + bbase);
                ldmx4t(fbh[1], sBh + bbase + 16 * 2);
                ldmx4t(fbl[0], sBl + bbase);
                ldmx4t(fbl[1], sBl + bbase + 16 * 2);
            } else {
                int bbase = ((wn * 32 + (lane & 7) + ((lane >> 4) & 1) * 8) * BST
                             + ((lane >> 3) & 1) * 8 + kk) * 2;
                ldmx4(fbh[0], sBh + bbase);
                ldmx4(fbh[1], sBh + bbase + 16 * BST * 2);
                ldmx4(fbl[0], sBl + bbase);
                ldmx4(fbl[1], sBl + bbase + 16 * BST * 2);
            }

            #pragma unroll
            for (int mf = 0; mf < 4; mf++)
                #pragma unroll
                for (int nf = 0; nf < 4; nf++) {
                    const uint32_t* bh2 = &fbh[nf >> 1][(nf & 1) * 2];
                    const uint32_t* bl2 = &fbl[nf >> 1][(nf & 1) * 2];
                    mma16816(c[mf][nf], fah[mf], bh2);   // hi*hi
                    mma16816(c[mf][nf], fah[mf], bl2);   // hi*lo
                    mma16816(c[mf][nf], fal[mf], bh2);   // lo*hi
                }
        }
        __syncthreads();
    }

    // ---- epilogue ----
    int g = lane >> 2, t = lane & 3;
    #pragma unroll
    for (int mf = 0; mf < 4; mf++) {
        #pragma unroll
        for (int nf = 0; nf < 4; nf++) {
            int r  = row0 + wm * 64 + mf * 16 + g;
            int cc = col0 + wn * 32 + nf * 8 + t * 2;
            float* p0 = C + (size_t)r * N + cc;
            float* p1 = C + (size_t)(r + 8) * N + cc;
            if (cc < N) {
                if (ACCUM) { p0[0] += c[mf][nf][0]; p1[0] += c[mf][nf][2]; }
                else       { p0[0]  = c[mf][nf][0]; p1[0]  = c[mf][nf][2]; }
            }
            if (cc + 1 < N) {
                if (ACCUM) { p0[1] += c[mf][nf][1]; p1[1] += c[mf][nf][3]; }
                else       { p0[1]  = c[mf][nf][1]; p1[1]  = c[mf][nf][3]; }
            }
        }
    }
}

// ---------------- RoPE ----------------
__global__ void rope_kernel() {
    int row = blockIdx.x;
    int t = row % TT;
    int i = threadIdx.x;                 // 480 = (12+3)*32
    int head = i >> 5;
    int d = i & 31;
    float freq = powf(10000.f, (float)d / 32.0f);
    float ang = (float)t / freq;
    float s, c;
    sincosf(ang, &s, &c);
    float* p;
    if (head < HH) p = g_q + (size_t)row * DD + head * HS;
    else           p = g_k + (size_t)row * KVD + (head - HH) * HS;
    float xr = p[d], xi = p[d + 32];
    p[d]      = xr * c - xi * s;
    p[d + 32] = xi * c + xr * s;
}

// ---------------- fused causal attention (online softmax, 64-query tiles) ----------------
#define ATN_STRIDE 68
#define ATN_SMEM   (3 * 64 * ATN_STRIDE * 4)

__global__ __launch_bounds__(256) void attn_kernel() {
    extern __shared__ float sm[];
    float (*Qs)[ATN_STRIDE]   = (float(*)[ATN_STRIDE])sm;
    float (*KtPs)[ATN_STRIDE] = (float(*)[ATN_STRIDE])(sm + 64 * ATN_STRIDE);
    float (*Vs)[ATN_STRIDE]   = (float(*)[ATN_STRIDE])(sm + 2 * 64 * ATN_STRIDE);

    int q0 = blockIdx.x * 64;
    int b = blockIdx.y / HH, h = blockIdx.y % HH;
    int kvh = h % NKV;
    int tid = threadIdx.x;
    int r = tid >> 2, g = tid & 3;

    #pragma unroll
    for (int i = 0; i < 4; i++) {
        int f = tid + i * 256;
        int rr = f >> 4, c4 = (f & 15) * 4;
        float4 v = *(const float4*)(g_q + (size_t)(b * TT + q0 + rr) * DD + h * HS + c4);
        Qs[rr][c4] = v.x; Qs[rr][c4 + 1] = v.y; Qs[rr][c4 + 2] = v.z; Qs[rr][c4 + 3] = v.w;
    }

    float O[16];
    #pragma unroll
    for (int j = 0; j < 16; j++) O[j] = 0.f;
    float m = -1e30f, l = 0.f;
    const float scale = 0.125f;

    for (int s0 = 0; s0 <= q0; s0 += 64) {
        __syncthreads();
        #pragma unroll
        for (int i = 0; i < 4; i++) {
            int f = tid + i * 256;
            int rr = f >> 4, c4 = (f & 15) * 4;
            size_t base = (size_t)(b * TT + s0 + rr) * KVD + kvh * HS + c4;
            float4 kv = *(const float4*)(g_k + base);
            KtPs[c4][rr] = kv.x; KtPs[c4 + 1][rr] = kv.y;
            KtPs[c4 + 2][rr] = kv.z; KtPs[c4 + 3][rr] = kv.w;
            float4 vv = *(const float4*)(g_v + base);
            Vs[rr][c4] = vv.x; Vs[rr][c4 + 1] = vv.y; Vs[rr][c4 + 2] = vv.z; Vs[rr][c4 + 3] = vv.w;
        }
        __syncthreads();

        float sv[16];
        #pragma unroll
        for (int j = 0; j < 16; j++) sv[j] = 0.f;
        #pragma unroll 4
        for (int d = 0; d < 64; d++) {
            float qd = Qs[r][d];
            #pragma unroll
            for (int j = 0; j < 16; j++) sv[j] += qd * KtPs[d][g * 16 + j];
        }
        #pragma unroll
        for (int j = 0; j < 16; j++) {
            int key = s0 + g * 16 + j;
            sv[j] = (key <= q0 + r) ? sv[j] * scale : -1e30f;
        }
        float mx = sv[0];
        #pragma unroll
        for (int j = 1; j < 16; j++) mx = fmaxf(mx, sv[j]);
        mx = fmaxf(mx, __shfl_xor_sync(0xffffffffu, mx, 1));
        mx = fmaxf(mx, __shfl_xor_sync(0xffffffffu, mx, 2));
        float m_new = fmaxf(m, mx);
        float corr = __expf(m - m_new);

        __syncthreads();

        float ssum = 0.f;
        #pragma unroll
        for (int j = 0; j < 16; j++) {
            float p = __expf(sv[j] - m_new);
            KtPs[r][g * 16 + j] = p;
            ssum += p;
        }
        ssum += __shfl_xor_sync(0xffffffffu, ssum, 1);
        ssum += __shfl_xor_sync(0xffffffffu, ssum, 2);
        l = l * corr + ssum;
        m = m_new;
        #pragma unroll
        for (int j = 0; j < 16; j++) O[j] *= corr;
        __syncwarp();

        #pragma unroll 4
        for (int s = 0; s < 64; s++) {
            float p = KtPs[r][s];
            #pragma unroll
            for (int j = 0; j < 16; j++) O[j] += p * Vs[s][g * 16 + j];
        }
    }

    float invl = 1.f / l;
    size_t obase = (size_t)(b * TT + q0 + r) * DD + h * HS + g * 16;
    #pragma unroll
    for (int j = 0; j < 16; j++) {
        float o = O[j] * invl;
        __nv_bfloat16 h2, l2;
        bf16_split(o, h2, l2);
        g_yh[obase + j] = h2;
        g_yl[obase + j] = l2;
    }
}

// ---------------- SiLU(gate) * up -> bf16 hi/lo ----------------
__global__ void silu_mul_kernel() {
    int i = blockIdx.x * 256 + threadIdx.x;
    float gv = g_gate[i];
    float r = gv / (1.f + __expf(-gv)) * g_up[i];
    __nv_bfloat16 h, l;
    bf16_split(r, h, l);
    g_ah[i] = h;
    g_al[i] = l;
}

// ---------------- host ----------------
static inline int sgrid(int n) { return (n / 4 + 255) / 256; }

extern "C" void kernel_launch(void* const* d_in, const int* in_sizes, int n_in,
                              void* d_out, int out_size) {
    const int*   idx   = (const int*)d_in[0];
    const float* embed = (const float*)d_in[1];
    const float* ln1   = (const float*)d_in[2];
    const float* qw    = (const float*)d_in[3];
    const float* kw    = (const float*)d_in[4];
    const float* vw    = (const float*)d_in[5];
    const float* ow    = (const float*)d_in[6];
    const float* ln2   = (const float*)d_in[7];
    const float* gw    = (const float*)d_in[8];
    const float* uw    = (const float*)d_in[9];
    const float* dw    = (const float*)d_in[10];
    const float* nw    = (const float*)d_in[11];
    float* out = (float*)d_out;

    float *px, *pq, *pk, *pv, *pg, *pu;
    cudaGetSymbolAddress((void**)&px, g_x);
    cudaGetSymbolAddress((void**)&pq, g_q);
    cudaGetSymbolAddress((void**)&pk, g_k);
    cudaGetSymbolAddress((void**)&pv, g_v);
    cudaGetSymbolAddress((void**)&pg, g_gate);
    cudaGetSymbolAddress((void**)&pu, g_up);

    __nv_bfloat16 *hh, *hl, *yh, *yl, *ah, *al;
    cudaGetSymbolAddress((void**)&hh, g_hh); cudaGetSymbolAddress((void**)&hl, g_hl);
    cudaGetSymbolAddress((void**)&yh, g_yh); cudaGetSymbolAddress((void**)&yl, g_yl);
    cudaGetSymbolAddress((void**)&ah, g_ah); cudaGetSymbolAddress((void**)&al, g_al);

    __nv_bfloat16 *qwh, *qwl, *kwh, *kwl, *vwh, *vwl, *owh, *owl;
    __nv_bfloat16 *gwh, *gwl, *uwh, *uwl, *dwh, *dwl, *emh, *eml;
    cudaGetSymbolAddress((void**)&qwh, s_qw_h); cudaGetSymbolAddress((void**)&qwl, s_qw_l);
    cudaGetSymbolAddress((void**)&kwh, s_kw_h); cudaGetSymbolAddress((void**)&kwl, s_kw_l);
    cudaGetSymbolAddress((void**)&vwh, s_vw_h); cudaGetSymbolAddress((void**)&vwl, s_vw_l);
    cudaGetSymbolAddress((void**)&owh, s_ow_h); cudaGetSymbolAddress((void**)&owl, s_ow_l);
    cudaGetSymbolAddress((void**)&gwh, s_gw_h); cudaGetSymbolAddress((void**)&gwl, s_gw_l);
    cudaGetSymbolAddress((void**)&uwh, s_uw_h); cudaGetSymbolAddress((void**)&uwl, s_uw_l);
    cudaGetSymbolAddress((void**)&dwh, s_dw_h); cudaGetSymbolAddress((void**)&dwl, s_dw_l);
    cudaGetSymbolAddress((void**)&emh, s_em_h); cudaGetSymbolAddress((void**)&eml, s_em_l);

    cudaFuncSetAttribute(attn_kernel, cudaFuncAttributeMaxDynamicSharedMemorySize, ATN_SMEM);

    // ---- prologue: split weights + embed to bf16 hi/lo ----
    split_kernel<<<sgrid(NL*DD*DD),  256>>>(qw, qwh, qwl, NL*DD*DD/4);
    split_kernel<<<sgrid(NL*DD*KVD), 256>>>(kw, kwh, kwl, NL*DD*KVD/4);
    split_kernel<<<sgrid(NL*DD*KVD), 256>>>(vw, vwh, vwl, NL*DD*KVD/4);
    split_kernel<<<sgrid(NL*DD*DD),  256>>>(ow, owh, owl, NL*DD*DD/4);
    split_kernel<<<sgrid(NL*DD*II),  256>>>(gw, gwh, gwl, NL*DD*II/4);
    split_kernel<<<sgrid(NL*DD*II),  256>>>(uw, uwh, uwl, NL*DD*II/4);
    split_kernel<<<sgrid(NL*II*DD),  256>>>(dw, dwh, dwl, NL*II*DD/4);
    split_kernel<<<sgrid(VV*DD),     256>>>(embed, emh, eml, VV*DD/4);

    dim3 gq(DD / 128, BT / 128);     // (6,16)
    dim3 gkv(KVD / 128 + 1, BT / 128); // (2,16) — col block 1 partially filled
    dim3 gi(II / 128, BT / 128);     // (16,16)
    dim3 ga(TT / 64, 2 * HH);        // (16,24)
    dim3 gl((VV + 127) / 128, BT / 128); // (393,16)

    embed_kernel<<<BT, 192>>>(idx, embed);

    for (int l = 0; l < NL; l++) {
        size_t oD = (size_t)l * DD * DD;
        size_t oK = (size_t)l * DD * KVD;
        size_t oI = (size_t)l * DD * II;

        rmsnorm_split<<<BT, 256>>>(px, ln1 + (size_t)l * DD, hh, hl);
        bgemm<0, 0><<<gq,  256>>>(hh, hl, qwh + oD, qwl + oD, pq, BT, DD,  DD);
        bgemm<0, 0><<<gkv, 256>>>(hh, hl, kwh + oK, kwl + oK, pk, BT, KVD, DD);
        bgemm<0, 0><<<gkv, 256>>>(hh, hl, vwh + oK, vwl + oK, pv, BT, KVD, DD);
        rope_kernel<<<BT, 480>>>();
        attn_kernel<<<ga, 256, ATN_SMEM>>>();
        bgemm<0, 1><<<gq, 256>>>(yh, yl, owh + oD, owl + oD, px, BT, DD, DD);   // x += y @ o_w
        rmsnorm_split<<<BT, 256>>>(px, ln2 + (size_t)l * DD, hh, hl);
        bgemm<0, 0><<<gi, 256>>>(hh, hl, gwh + oI, gwl + oI, pg, BT, II, DD);
        bgemm<0, 0><<<gi, 256>>>(hh, hl, uwh + oI, uwl + oI, pu, BT, II, DD);
        silu_mul_kernel<<<(BT * II) / 256, 256>>>();
        bgemm<0, 1><<<gq, 256>>>(ah, al, dwh + oI, dwl + oI, px, BT, DD, II);   // x += mlp
    }

    rmsnorm_split<<<BT, 256>>>(px, nw, hh, hl);
    bgemm<1, 0><<<gl, 256>>>(hh, hl, emh, eml, out, BT, VV, DD);                 // logits
}

// round 7
// speedup vs baseline: 3.9940x; 2.5100x over previous
#include <cuda_runtime.h>
#include <cuda_bf16.h>
#include <math.h>
#include <stdint.h>

// Problem constants
#define BT   2048
#define TT   1024
#define DD   768
#define HH   12
#define HS   64
#define NKV  3
#define NL   12
#define II   2048
#define VV   50257
#define KVD  192
#define QKV  1152     // 768 q + 192 k + 192 v
#define GU   4096     // 2048 gate + 2048 up
#define EPS_ 1e-6f

// ---------------- fp32 scratch ----------------
__device__ float g_x[BT * DD];
__device__ float g_qkv[BT * QKV];
__device__ float g_gu[BT * GU];

// ---------------- bf16 split activations ----------------
__device__ __nv_bfloat16 g_hh[BT * DD],  g_hl[BT * DD];    // rmsnorm out
__device__ __nv_bfloat16 g_qkvh[BT * QKV], g_qkvl[BT * QKV];
__device__ __nv_bfloat16 g_yh[BT * DD],  g_yl[BT * DD];    // attention out
__device__ __nv_bfloat16 g_ah[BT * II],  g_al[BT * II];    // silu*up out

// ---------------- bf16 split weights (prologue) ----------------
__device__ __nv_bfloat16 s_qkvw_h[NL * DD * QKV], s_qkvw_l[NL * DD * QKV];
__device__ __nv_bfloat16 s_ow_h[NL * DD * DD],    s_ow_l[NL * DD * DD];
__device__ __nv_bfloat16 s_guw_h[NL * DD * GU],   s_guw_l[NL * DD * GU];
__device__ __nv_bfloat16 s_dw_h[NL * II * DD],    s_dw_l[NL * II * DD];
__device__ __nv_bfloat16 s_em_h[(size_t)VV * DD], s_em_l[(size_t)VV * DD];

// ---------------- helpers ----------------
__device__ __forceinline__ void bf16_split(float v, __nv_bfloat16& h, __nv_bfloat16& l) {
    h = __float2bfloat16(v);
    l = __float2bfloat16(v - __bfloat162float(h));
}
__device__ __forceinline__ uint32_t packbf(__nv_bfloat16 a, __nv_bfloat16 b) {
    __nv_bfloat162 t = __halves2bfloat162(a, b);
    return *(uint32_t*)&t;
}
__device__ __forceinline__ void ldmx4(uint32_t* r, uint32_t a) {
    asm volatile("ldmatrix.sync.aligned.m8n8.x4.shared.b16 {%0,%1,%2,%3}, [%4];"
                 : "=r"(r[0]), "=r"(r[1]), "=r"(r[2]), "=r"(r[3]) : "r"(a));
}
__device__ __forceinline__ void ldmx4t(uint32_t* r, uint32_t a) {
    asm volatile("ldmatrix.sync.aligned.m8n8.x4.trans.shared.b16 {%0,%1,%2,%3}, [%4];"
                 : "=r"(r[0]), "=r"(r[1]), "=r"(r[2]), "=r"(r[3]) : "r"(a));
}
__device__ __forceinline__ void mma16816(float* c, const uint32_t* a, const uint32_t* b) {
    asm volatile("mma.sync.aligned.m16n8k16.row.col.f32.bf16.bf16.f32 "
                 "{%0,%1,%2,%3}, {%4,%5,%6,%7}, {%8,%9}, {%0,%1,%2,%3};"
                 : "+f"(c[0]), "+f"(c[1]), "+f"(c[2]), "+f"(c[3])
                 : "r"(a[0]), "r"(a[1]), "r"(a[2]), "r"(a[3]), "r"(b[0]), "r"(b[1]));
}
__device__ __forceinline__ void cpa16(uint32_t dst, const void* src) {
    asm volatile("cp.async.cg.shared.global [%0], [%1], 16;" :: "r"(dst), "l"(src));
}
__device__ __forceinline__ void cpcommit() { asm volatile("cp.async.commit_group;"); }
template<int N> __device__ __forceinline__ void cpwait() {
    asm volatile("cp.async.wait_group %0;" :: "n"(N));
}

// ---------------- fp32 -> bf16 hi/lo splitter ----------------
__global__ void split_kernel(const float* __restrict__ s,
                             __nv_bfloat16* __restrict__ h,
                             __nv_bfloat16* __restrict__ l, int n4) {
    int i = blockIdx.x * 256 + threadIdx.x;
    if (i >= n4) return;
    float4 v = ((const float4*)s)[i];
    __nv_bfloat16 h0, h1, h2, h3, l0, l1, l2, l3;
    bf16_split(v.x, h0, l0); bf16_split(v.y, h1, l1);
    bf16_split(v.z, h2, l2); bf16_split(v.w, h3, l3);
    __nv_bfloat162* hp = (__nv_bfloat162*)(h + (size_t)i * 4);
    __nv_bfloat162* lp = (__nv_bfloat162*)(l + (size_t)i * 4);
    hp[0] = __halves2bfloat162(h0, h1); hp[1] = __halves2bfloat162(h2, h3);
    lp[0] = __halves2bfloat162(l0, l1); lp[1] = __halves2bfloat162(l2, l3);
}

// ---------------- prologue: pack qkv weights [D][1152] ----------------
__global__ void pack_qkv4(const float* __restrict__ qw, const float* __restrict__ kw,
                          const float* __restrict__ vw) {
    int i4 = blockIdx.x * 256 + threadIdx.x;           // NL*DD*288
    int c4 = (i4 % 288) * 4;
    int rl = i4 / 288;
    int row = rl % DD, l = rl / DD;
    const float* src;
    if (c4 < DD)            src = qw + ((size_t)l * DD + row) * DD + c4;
    else if (c4 < DD + KVD) src = kw + ((size_t)l * DD + row) * KVD + (c4 - DD);
    else                    src = vw + ((size_t)l * DD + row) * KVD + (c4 - DD - KVD);
    float4 v = *(const float4*)src;
    __nv_bfloat16 h0, h1, h2, h3, l0, l1, l2, l3;
    bf16_split(v.x, h0, l0); bf16_split(v.y, h1, l1);
    bf16_split(v.z, h2, l2); bf16_split(v.w, h3, l3);
    __nv_bfloat162* hp = (__nv_bfloat162*)(s_qkvw_h + (size_t)i4 * 4);
    __nv_bfloat162* lp = (__nv_bfloat162*)(s_qkvw_l + (size_t)i4 * 4);
    hp[0] = __halves2bfloat162(h0, h1); hp[1] = __halves2bfloat162(h2, h3);
    lp[0] = __halves2bfloat162(l0, l1); lp[1] = __halves2bfloat162(l2, l3);
}

// ---------------- prologue: pack gate/up weights [D][4096] ----------------
__global__ void pack_gu4(const float* __restrict__ gw, const float* __restrict__ uw) {
    int i4 = blockIdx.x * 256 + threadIdx.x;           // NL*DD*1024
    int c4 = (i4 & 1023) * 4;
    int rl = i4 >> 10;
    int row = rl % DD, l = rl / DD;
    const float* src;
    if (c4 < II) src = gw + ((size_t)l * DD + row) * II + c4;
    else         src = uw + ((size_t)l * DD + row) * II + (c4 - II);
    float4 v = *(const float4*)src;
    __nv_bfloat16 h0, h1, h2, h3, l0, l1, l2, l3;
    bf16_split(v.x, h0, l0); bf16_split(v.y, h1, l1);
    bf16_split(v.z, h2, l2); bf16_split(v.w, h3, l3);
    __nv_bfloat162* hp = (__nv_bfloat162*)(s_guw_h + (size_t)i4 * 4);
    __nv_bfloat162* lp = (__nv_bfloat162*)(s_guw_l + (size_t)i4 * 4);
    hp[0] = __halves2bfloat162(h0, h1); hp[1] = __halves2bfloat162(h2, h3);
    lp[0] = __halves2bfloat162(l0, l1); lp[1] = __halves2bfloat162(l2, l3);
}

// ---------------- embedding gather ----------------
__global__ void embed_kernel(const int* __restrict__ idx,
                             const float* __restrict__ embed) {
    int row = blockIdx.x;
    int t4  = threadIdx.x;
    const float4* src = (const float4*)(embed + (size_t)idx[row] * DD);
    ((float4*)(g_x + (size_t)row * DD))[t4] = src[t4];
}

// ---------------- RMSNorm -> bf16 hi/lo ----------------
__global__ __launch_bounds__(256) void rmsnorm_split(const float* __restrict__ in,
                                                     const float* __restrict__ w,
                                                     __nv_bfloat16* __restrict__ oh,
                                                     __nv_bfloat16* __restrict__ ol) {
    int row = blockIdx.x;
    const float* x = in + (size_t)row * DD;
    float s = 0.f;
    for (int i = threadIdx.x; i < DD; i += 256) { float v = x[i]; s += v * v; }
    #pragma unroll
    for (int o = 16; o; o >>= 1) s += __shfl_xor_sync(0xffffffffu, s, o);
    __shared__ float red[8];
    if ((threadIdx.x & 31) == 0) red[threadIdx.x >> 5] = s;
    __syncthreads();
    if (threadIdx.x < 8) {
        s = red[threadIdx.x];
        #pragma unroll
        for (int o = 4; o; o >>= 1) s += __shfl_xor_sync(0xffu, s, o);
        if (threadIdx.x == 0) red[0] = s;
    }
    __syncthreads();
    float inv = rsqrtf(red[0] / (float)DD + EPS_);
    for (int i = threadIdx.x; i < DD; i += 256) {
        float r = w[i] * x[i] * inv;
        __nv_bfloat16 h, l;
        bf16_split(r, h, l);
        oh[(size_t)row * DD + i] = h;
        ol[(size_t)row * DD + i] = l;
    }
}

// ---------------- bf16x3 tensor-core GEMM, cp.async double-buffered ----------------
// C[M,N] = A[M,K] @ B (+C if ACCUM). TRANSB==0: B[K,N]; TRANSB==1: B[N,K].
// Block tile 128x128, BK=32, 2 stages. 8 warps 2x4, warp tile 64x32.
template<int TRANSB, int ACCUM>
__global__ __launch_bounds__(256) void bgemm(const __nv_bfloat16* __restrict__ Ah,
                                             const __nv_bfloat16* __restrict__ Al,
                                             const __nv_bfloat16* __restrict__ Bh,
                                             const __nv_bfloat16* __restrict__ Bl,
                                             float* __restrict__ C,
                                             int M, int N, int K) {
    constexpr int AST   = 40;
    constexpr int BROWS = TRANSB ? 128 : 32;
    constexpr int BST   = TRANSB ? 40  : 136;
    constexpr int ASZ   = 128 * AST;
    constexpr int BSZ   = BROWS * BST;
    constexpr int STG   = 2 * ASZ + 2 * BSZ;      // elems per stage

    extern __shared__ __nv_bfloat16 smem[];
    int tid  = threadIdx.x;
    int lane = tid & 31, wid = tid >> 5;
    int wm = wid >> 2, wn = wid & 3;
    int row0 = blockIdx.y * 128, col0 = blockIdx.x * 128;

    float c[4][4][4] = {};
    uint32_t sbase = (uint32_t)__cvta_generic_to_shared(smem);

    int am = tid >> 2, aq = (tid & 3) * 8;

    auto load_stage = [&](int st, int k0) {
        uint32_t aoff = sbase + (uint32_t)st * STG * 2;
        #pragma unroll
        for (int i = 0; i < 2; i++) {
            int m = am + i * 64;
            size_t g = (size_t)(row0 + m) * K + k0 + aq;
            cpa16(aoff + (m * AST + aq) * 2, Ah + g);
            cpa16(aoff + (ASZ + m * AST + aq) * 2, Al + g);
        }
        uint32_t boff = aoff + 2 * ASZ * 2;
        if (!TRANSB) {
            #pragma unroll
            for (int i = 0; i < 2; i++) {
                int k = (tid >> 4) + i * 16, q = (tid & 15) * 8;
                size_t g = (size_t)(k0 + k) * N + col0 + q;   // N % 128 == 0 here
                cpa16(boff + (k * BST + q) * 2, Bh + g);
                cpa16(boff + (BSZ + k * BST + q) * 2, Bl + g);
            }
        } else {
            #pragma unroll
            for (int i = 0; i < 2; i++) {
                int n = (tid >> 2) + i * 64, q = (tid & 3) * 8;
                if (col0 + n < N) {
                    size_t g = (size_t)(col0 + n) * K + k0 + q;
                    cpa16(boff + (n * BST + q) * 2, Bh + g);
                    cpa16(boff + (BSZ + n * BST + q) * 2, Bl + g);
                }
            }
        }
    };

    int nit = K / 32;
    load_stage(0, 0);
    cpcommit();

    for (int it = 0; it < nit; it++) {
        int cur = it & 1;
        if (it + 1 < nit) { load_stage(cur ^ 1, (it + 1) * 32); cpcommit(); cpwait<1>(); }
        else              { cpwait<0>(); }
        __syncthreads();

        uint32_t sA   = sbase + (uint32_t)cur * STG * 2;
        uint32_t sAl_ = sA + ASZ * 2;
        uint32_t sB   = sA + 2 * ASZ * 2;
        uint32_t sBl_ = sB + BSZ * 2;

        #pragma unroll
        for (int kk = 0; kk < 32; kk += 16) {
            uint32_t fah[4][4], fal[4][4], fbh[2][4], fbl[2][4];
            int abase = ((wm * 64 + (lane & 15)) * AST + (lane >> 4) * 8 + kk) * 2;
            #pragma unroll
            for (int mf = 0; mf < 4; mf++) {
                ldmx4(fah[mf], sA   + abase + mf * 16 * AST * 2);
                ldmx4(fal[mf], sAl_ + abase + mf * 16 * AST * 2);
            }
            if (!TRANSB) {
                int bbase = (((lane & 7) + ((lane >> 3) & 1) * 8 + kk) * BST
                             + wn * 32 + ((lane >> 4) & 1) * 8) * 2;
                ldmx4t(fbh[0], sB + bbase);   ldmx4t(fbh[1], sB + bbase + 32);
                ldmx4t(fbl[0], sBl_ + bbase); ldmx4t(fbl[1], sBl_ + bbase + 32);
            } else {
                int bbase = ((wn * 32 + (lane & 7) + ((lane >> 4) & 1) * 8) * BST
                             + ((lane >> 3) & 1) * 8 + kk) * 2;
                ldmx4(fbh[0], sB + bbase);   ldmx4(fbh[1], sB + bbase + 16 * BST * 2);
                ldmx4(fbl[0], sBl_ + bbase); ldmx4(fbl[1], sBl_ + bbase + 16 * BST * 2);
            }
            #pragma unroll
            for (int mf = 0; mf < 4; mf++)
                #pragma unroll
                for (int nf = 0; nf < 4; nf++) {
                    const uint32_t* bh2 = &fbh[nf >> 1][(nf & 1) * 2];
                    const uint32_t* bl2 = &fbl[nf >> 1][(nf & 1) * 2];
                    mma16816(c[mf][nf], fah[mf], bh2);
                    mma16816(c[mf][nf], fah[mf], bl2);
                    mma16816(c[mf][nf], fal[mf], bh2);
                }
        }
        __syncthreads();
    }

    int g = lane >> 2, t = lane & 3;
    #pragma unroll
    for (int mf = 0; mf < 4; mf++) {
        #pragma unroll
        for (int nf = 0; nf < 4; nf++) {
            int r  = row0 + wm * 64 + mf * 16 + g;
            int cc = col0 + wn * 32 + nf * 8 + t * 2;
            float* p0 = C + (size_t)r * N + cc;
            float* p1 = C + (size_t)(r + 8) * N + cc;
            if (cc < N) {
                if (ACCUM) { p0[0] += c[mf][nf][0]; p1[0] += c[mf][nf][2]; }
                else       { p0[0]  = c[mf][nf][0]; p1[0]  = c[mf][nf][2]; }
            }
            if (cc + 1 < N) {
                if (ACCUM) { p0[1] += c[mf][nf][1]; p1[1] += c[mf][nf][3]; }
                else       { p0[1]  = c[mf][nf][1]; p1[1]  = c[mf][nf][3]; }
            }
        }
    }
}

// ---------------- RoPE in fused qkv buffer; q scaled by 1/sqrt(HS) ----------------
__global__ void rope_kernel() {
    int row = blockIdx.x;
    int t = row % TT;
    int i = threadIdx.x;                 // 480 = (12+3)*32
    int head = i >> 5;
    int d = i & 31;
    float freq = powf(10000.f, (float)d / 32.0f);
    float ang = (float)t / freq;
    float s, c;
    sincosf(ang, &s, &c);
    float* p;
    float sc;
    if (head < HH) { p = g_qkv + (size_t)row * QKV + head * HS;                sc = 0.125f; }
    else           { p = g_qkv + (size_t)row * QKV + DD + (head - HH) * HS;    sc = 1.0f;   }
    float xr = p[d], xi = p[d + 32];
    p[d]      = (xr * c - xi * s) * sc;
    p[d + 32] = (xi * c + xr * s) * sc;
}

// ---------------- flash attention, bf16x3 mma, 128-query tiles ----------------
// grid (TT/128, B*HH), 256 threads (8 warps; warp w owns rows w*16..w*16+15)
#define AT_ST 72
#define ATN_SMEM ((2 * 128 * AT_ST + 4 * 64 * AT_ST) * 2)   // bytes

__global__ __launch_bounds__(256) void attn_mma() {
    extern __shared__ __nv_bfloat16 sm[];
    __nv_bfloat16* Qh = sm;
    __nv_bfloat16* Ql = Qh + 128 * AT_ST;
    __nv_bfloat16* Kh = Ql + 128 * AT_ST;
    __nv_bfloat16* Kl = Kh + 64 * AT_ST;
    __nv_bfloat16* Vh = Kl + 64 * AT_ST;
    __nv_bfloat16* Vl = Vh + 64 * AT_ST;

    int tid = threadIdx.x, lane = tid & 31, w = tid >> 5;
    int q0 = blockIdx.x * 128;
    int b = blockIdx.y / HH, h = blockIdx.y % HH, kvh = h % NKV;

    uint32_t sQh = (uint32_t)__cvta_generic_to_shared(Qh);
    uint32_t sQl = (uint32_t)__cvta_generic_to_shared(Ql);
    uint32_t sKh = (uint32_t)__cvta_generic_to_shared(Kh);
    uint32_t sKl = (uint32_t)__cvta_generic_to_shared(Kl);
    uint32_t sVh = (uint32_t)__cvta_generic_to_shared(Vh);
    uint32_t sVl = (uint32_t)__cvta_generic_to_shared(Vl);

    // load Q tile (already scaled by 0.125 in rope)
    for (int i = tid; i < 128 * 8; i += 256) {
        int row = i >> 3, q8 = (i & 7) * 8;
        size_t g = (size_t)(b * TT + q0 + row) * QKV + h * HS + q8;
        *(uint4*)&Qh[row * AT_ST + q8] = *(const uint4*)&g_qkvh[g];
        *(uint4*)&Ql[row * AT_ST + q8] = *(const uint4*)&g_qkvl[g];
    }
    __syncthreads();

    uint32_t qfh[4][4], qfl[4][4];
    {
        int abase = ((w * 16 + (lane & 15)) * AT_ST + (lane >> 4) * 8) * 2;
        #pragma unroll
        for (int kp = 0; kp < 4; kp++) {
            ldmx4(qfh[kp], sQh + abase + kp * 32);
            ldmx4(qfl[kp], sQl + abase + kp * 32);
        }
    }

    float m0 = -1e30f, m1 = -1e30f, l0 = 0.f, l1 = 0.f;
    float co[8][4] = {};
    int r_seq = q0 + w * 16 + (lane >> 2);
    int nt = q0 / 64 + 2;

    for (int it = 0; it < nt; it++) {
        int s0 = it * 64;
        __syncthreads();
        for (int i = tid; i < 64 * 8; i += 256) {
            int row = i >> 3, q8 = (i & 7) * 8;
            size_t gk = (size_t)(b * TT + s0 + row) * QKV + DD + kvh * HS + q8;
            size_t gv = gk + KVD;
            *(uint4*)&Kh[row * AT_ST + q8] = *(const uint4*)&g_qkvh[gk];
            *(uint4*)&Kl[row * AT_ST + q8] = *(const uint4*)&g_qkvl[gk];
            *(uint4*)&Vh[row * AT_ST + q8] = *(const uint4*)&g_qkvh[gv];
            *(uint4*)&Vl[row * AT_ST + q8] = *(const uint4*)&g_qkvl[gv];
        }
        __syncthreads();

        // S = Q K^T  (keys as n, dims as k) — TRANSB=1 fragment pattern
        float cs[8][4] = {};
        #pragma unroll
        for (int kp = 0; kp < 4; kp++) {
            #pragma unroll
            for (int ng = 0; ng < 4; ng++) {
                uint32_t bh[4], bl[4];
                int bbase = ((ng * 16 + (lane & 7) + ((lane >> 4) & 1) * 8) * AT_ST
                             + ((lane >> 3) & 1) * 8 + kp * 16) * 2;
                ldmx4(bh, sKh + bbase);
                ldmx4(bl, sKl + bbase);
                mma16816(cs[2 * ng],     qfh[kp], &bh[0]);
                mma16816(cs[2 * ng],     qfh[kp], &bl[0]);
                mma16816(cs[2 * ng],     qfl[kp], &bh[0]);
                mma16816(cs[2 * ng + 1], qfh[kp], &bh[2]);
                mma16816(cs[2 * ng + 1], qfh[kp], &bl[2]);
                mma16816(cs[2 * ng + 1], qfl[kp], &bh[2]);
            }
        }

        // causal mask (only tiles that can intersect the diagonal of this warp)
        if (s0 + 63 > q0 + w * 16) {
            #pragma unroll
            for (int nf = 0; nf < 8; nf++) {
                int key = s0 + nf * 8 + (lane & 3) * 2;
                if (key     > r_seq)     cs[nf][0] = -1e30f;
                if (key + 1 > r_seq)     cs[nf][1] = -1e30f;
                if (key     > r_seq + 8) cs[nf][2] = -1e30f;
                if (key + 1 > r_seq + 8) cs[nf][3] = -1e30f;
            }
        }

        // online softmax over 2 rows per thread
        float mx0 = cs[0][0], mx1 = cs[0][2];
        #pragma unroll
        for (int nf = 0; nf < 8; nf++) {
            mx0 = fmaxf(mx0, fmaxf(cs[nf][0], cs[nf][1]));
            mx1 = fmaxf(mx1, fmaxf(cs[nf][2], cs[nf][3]));
        }
        mx0 = fmaxf(mx0, __shfl_xor_sync(0xffffffffu, mx0, 1));
        mx0 = fmaxf(mx0, __shfl_xor_sync(0xffffffffu, mx0, 2));
        mx1 = fmaxf(mx1, __shfl_xor_sync(0xffffffffu, mx1, 1));
        mx1 = fmaxf(mx1, __shfl_xor_sync(0xffffffffu, mx1, 2));
        float nm0 = fmaxf(m0, mx0), nm1 = fmaxf(m1, mx1);
        float corr0 = __expf(m0 - nm0), corr1 = __expf(m1 - nm1);
        m0 = nm0; m1 = nm1;

        uint32_t pfh[4][4], pfl[4][4];
        float sum0 = 0.f, sum1 = 0.f;
        #pragma unroll
        for (int nf = 0; nf < 8; nf++) {
            float p0 = __expf(cs[nf][0] - nm0), p1 = __expf(cs[nf][1] - nm0);
            float p2 = __expf(cs[nf][2] - nm1), p3 = __expf(cs[nf][3] - nm1);
            sum0 += p0 + p1; sum1 += p2 + p3;
            __nv_bfloat16 h0, lo0, h1, lo1, h2, lo2, h3, lo3;
            bf16_split(p0, h0, lo0); bf16_split(p1, h1, lo1);
            bf16_split(p2, h2, lo2); bf16_split(p3, h3, lo3);
            int kp = nf >> 1, o = (nf & 1) * 2;
            pfh[kp][o]     = packbf(h0, h1);  pfh[kp][o + 1] = packbf(h2, h3);
            pfl[kp][o]     = packbf(lo0, lo1); pfl[kp][o + 1] = packbf(lo2, lo3);
        }
        sum0 += __shfl_xor_sync(0xffffffffu, sum0, 1);
        sum0 += __shfl_xor_sync(0xffffffffu, sum0, 2);
        sum1 += __shfl_xor_sync(0xffffffffu, sum1, 1);
        sum1 += __shfl_xor_sync(0xffffffffu, sum1, 2);
        l0 = l0 * corr0 + sum0;
        l1 = l1 * corr1 + sum1;
        #pragma unroll
        for (int nf = 0; nf < 8; nf++) {
            co[nf][0] *= corr0; co[nf][1] *= corr0;
            co[nf][2] *= corr1; co[nf][3] *= corr1;
        }

        // O += P V  (keys as k, dims as n) — TRANSB=0 fragment pattern
        #pragma unroll
        for (int kp = 0; kp < 4; kp++) {
            #pragma unroll
            for (int ng = 0; ng < 4; ng++) {
                uint32_t bh[4], bl[4];
                int bbase = (((lane & 7) + ((lane >> 3) & 1) * 8 + kp * 16) * AT_ST
                             + ng * 16 + ((lane >> 4) & 1) * 8) * 2;
                ldmx4t(bh, sVh + bbase);
                ldmx4t(bl, sVl + bbase);
                mma16816(co[2 * ng],     pfh[kp], &bh[0]);
                mma16816(co[2 * ng],     pfh[kp], &bl[0]);
                mma16816(co[2 * ng],     pfl[kp], &bh[0]);
                mma16816(co[2 * ng + 1], pfh[kp], &bh[2]);
                mma16816(co[2 * ng + 1], pfh[kp], &bl[2]);
                mma16816(co[2 * ng + 1], pfl[kp], &bh[2]);
            }
        }
    }

    float il0 = 1.f / l0, il1 = 1.f / l1;
    size_t base0 = (size_t)(b * TT + r_seq) * DD + h * HS;
    size_t base1 = base0 + (size_t)8 * DD;
    #pragma unroll
    for (int nf = 0; nf < 8; nf++) {
        int cc = nf * 8 + (lane & 3) * 2;
        float y0 = co[nf][0] * il0, y1 = co[nf][1] * il0;
        float y2 = co[nf][2] * il1, y3 = co[nf][3] * il1;
        __nv_bfloat16 h0, lo0, h1, lo1, h2, lo2, h3, lo3;
        bf16_split(y0, h0, lo0); bf16_split(y1, h1, lo1);
        bf16_split(y2, h2, lo2); bf16_split(y3, h3, lo3);
        *(__nv_bfloat162*)&g_yh[base0 + cc] = __halves2bfloat162(h0, h1);
        *(__nv_bfloat162*)&g_yl[base0 + cc] = __halves2bfloat162(lo0, lo1);
        *(__nv_bfloat162*)&g_yh[base1 + cc] = __halves2bfloat162(h2, h3);
        *(__nv_bfloat162*)&g_yl[base1 + cc] = __halves2bfloat162(lo2, lo3);
    }
}

// ---------------- SiLU(gate) * up -> bf16 hi/lo (float4) ----------------
__global__ void silu_mul_kernel() {
    int i4 = blockIdx.x * 256 + threadIdx.x;     // BT*II/4
    int row = i4 >> 9;
    int col = (i4 & 511) * 4;
    float4 gv = *(const float4*)&g_gu[(size_t)row * GU + col];
    float4 uv = *(const float4*)&g_gu[(size_t)row * GU + II + col];
    float r0 = gv.x / (1.f + __expf(-gv.x)) * uv.x;
    float r1 = gv.y / (1.f + __expf(-gv.y)) * uv.y;
    float r2 = gv.z / (1.f + __expf(-gv.z)) * uv.z;
    float r3 = gv.w / (1.f + __expf(-gv.w)) * uv.w;
    __nv_bfloat16 h0, l0, h1, l1, h2, l2, h3, l3;
    bf16_split(r0, h0, l0); bf16_split(r1, h1, l1);
    bf16_split(r2, h2, l2); bf16_split(r3, h3, l3);
    size_t o = (size_t)row * II + col;
    *(__nv_bfloat162*)&g_ah[o]     = __halves2bfloat162(h0, h1);
    *(__nv_bfloat162*)&g_ah[o + 2] = __halves2bfloat162(h2, h3);
    *(__nv_bfloat162*)&g_al[o]     = __halves2bfloat162(l0, l1);
    *(__nv_bfloat162*)&g_al[o + 2] = __halves2bfloat162(l2, l3);
}

// ---------------- host ----------------
static inline int sgrid(size_t n4) { return (int)((n4 + 255) / 256); }

extern "C" void kernel_launch(void* const* d_in, const int* in_sizes, int n_in,
                              void* d_out, int out_size) {
    const int*   idx   = (const int*)d_in[0];
    const float* embed = (const float*)d_in[1];
    const float* ln1   = (const float*)d_in[2];
    const float* qw    = (const float*)d_in[3];
    const float* kw    = (const float*)d_in[4];
    const float* vw    = (const float*)d_in[5];
    const float* ow    = (const float*)d_in[6];
    const float* ln2   = (const float*)d_in[7];
    const float* gw    = (const float*)d_in[8];
    const float* uw    = (const float*)d_in[9];
    const float* dw    = (const float*)d_in[10];
    const float* nw    = (const float*)d_in[11];
    float* out = (float*)d_out;

    float *px, *pqkv, *pgu;
    cudaGetSymbolAddress((void**)&px,   g_x);
    cudaGetSymbolAddress((void**)&pqkv, g_qkv);
    cudaGetSymbolAddress((void**)&pgu,  g_gu);

    __nv_bfloat16 *hh, *hl, *yh, *yl, *ah, *al, *qvh, *qvl;
    cudaGetSymbolAddress((void**)&hh,  g_hh);  cudaGetSymbolAddress((void**)&hl,  g_hl);
    cudaGetSymbolAddress((void**)&yh,  g_yh);  cudaGetSymbolAddress((void**)&yl,  g_yl);
    cudaGetSymbolAddress((void**)&ah,  g_ah);  cudaGetSymbolAddress((void**)&al,  g_al);
    cudaGetSymbolAddress((void**)&qvh, g_qkvh); cudaGetSymbolAddress((void**)&qvl, g_qkvl);

    __nv_bfloat16 *qkvwh, *qkvwl, *owh, *owl, *guwh, *guwl, *dwh, *dwl, *emh, *eml;
    cudaGetSymbolAddress((void**)&qkvwh, s_qkvw_h); cudaGetSymbolAddress((void**)&qkvwl, s_qkvw_l);
    cudaGetSymbolAddress((void**)&owh, s_ow_h);     cudaGetSymbolAddress((void**)&owl, s_ow_l);
    cudaGetSymbolAddress((void**)&guwh, s_guw_h);   cudaGetSymbolAddress((void**)&guwl, s_guw_l);
    cudaGetSymbolAddress((void**)&dwh, s_dw_h);     cudaGetSymbolAddress((void**)&dwl, s_dw_l);
    cudaGetSymbolAddress((void**)&emh, s_em_h);     cudaGetSymbolAddress((void**)&eml, s_em_l);

    // dynamic smem opt-in
    const int SM_G0 = (2 * (128 * 40) + 2 * (32 * 136)) * 2 * 2;   // 75776 B
    const int SM_G1 = (2 * (128 * 40) + 2 * (128 * 40)) * 2 * 2;   // 81920 B
    cudaFuncSetAttribute(bgemm<0, 0>, cudaFuncAttributeMaxDynamicSharedMemorySize, SM_G0);
    cudaFuncSetAttribute(bgemm<0, 1>, cudaFuncAttributeMaxDynamicSharedMemorySize, SM_G0);
    cudaFuncSetAttribute(bgemm<1, 0>, cudaFuncAttributeMaxDynamicSharedMemorySize, SM_G1);
    cudaFuncSetAttribute(attn_mma,    cudaFuncAttributeMaxDynamicSharedMemorySize, ATN_SMEM);

    // ---- prologue: pack/split weights ----
    pack_qkv4<<<NL * DD * 288 / 256, 256>>>(qw, kw, vw);
    pack_gu4 <<<NL * DD * 1024 / 256, 256>>>(gw, uw);
    split_kernel<<<sgrid((size_t)NL * DD * DD / 4), 256>>>(ow, owh, owl, NL * DD * DD / 4);
    split_kernel<<<sgrid((size_t)NL * II * DD / 4), 256>>>(dw, dwh, dwl, NL * II * DD / 4);
    split_kernel<<<sgrid((size_t)VV * DD / 4), 256>>>(embed, emh, eml, VV * DD / 4);

    dim3 gqkv(QKV / 128, BT / 128);        // (9,16)
    dim3 go(DD / 128, BT / 128);           // (6,16)
    dim3 ggu(GU / 128, BT / 128);          // (32,16)
    dim3 ga(TT / 128, 2 * HH);             // (8,24)
    dim3 gl((VV + 127) / 128, BT / 128);   // (393,16)

    embed_kernel<<<BT, 192>>>(idx, embed);

    for (int l = 0; l < NL; l++) {
        size_t oQ = (size_t)l * DD * QKV;
        size_t oO = (size_t)l * DD * DD;
        size_t oG = (size_t)l * DD * GU;
        size_t oD2 = (size_t)l * II * DD;

        rmsnorm_split<<<BT, 256>>>(px, ln1 + (size_t)l * DD, hh, hl);
        bgemm<0, 0><<<gqkv, 256, SM_G0>>>(hh, hl, qkvwh + oQ, qkvwl + oQ, pqkv, BT, QKV, DD);
        rope_kernel<<<BT, 480>>>();
        split_kernel<<<sgrid((size_t)BT * QKV / 4), 256>>>(pqkv, qvh, qvl, BT * QKV / 4);
        attn_mma<<<ga, 256, ATN_SMEM>>>();
        bgemm<0, 1><<<go, 256, SM_G0>>>(yh, yl, owh + oO, owl + oO, px, BT, DD, DD);
        rmsnorm_split<<<BT, 256>>>(px, ln2 + (size_t)l * DD, hh, hl);
        bgemm<0, 0><<<ggu, 256, SM_G0>>>(hh, hl, guwh + oG, guwl + oG, pgu, BT, GU, DD);
        silu_mul_kernel<<<BT * II / 4 / 256, 256>>>();
        bgemm<0, 1><<<go, 256, SM_G0>>>(ah, al, dwh + oD2, dwl + oD2, px, BT, DD, II);
    }

    rmsnorm_split<<<BT, 256>>>(px, nw, hh, hl);
    bgemm<1, 0><<<gl, 256, SM_G1>>>(hh, hl, emh, eml, out, BT, VV, DD);
}